// round 1
// baseline (speedup 1.0000x reference)
#include <cuda_runtime.h>

typedef unsigned long long u64;

#define NT 128

// ---------------- packed f32x2 helpers ----------------
__device__ __forceinline__ u64 ffma2(u64 a, u64 b, u64 c) {
    u64 d;
    asm("fma.rn.f32x2 %0, %1, %2, %3;" : "=l"(d) : "l"(a), "l"(b), "l"(c));
    return d;
}
__device__ __forceinline__ u64 pk2(float lo, float hi) {
    u64 r;
    asm("mov.b64 %0, {%1, %2};" : "=l"(r) : "f"(lo), "f"(hi));
    return r;
}
__device__ __forceinline__ float2 unpk(u64 v) {
    float2 f;
    asm("mov.b64 {%0, %1}, %2;" : "=f"(f.x), "=f"(f.y) : "l"(v));
    return f;
}

// ---------------- shared memory byte offsets ----------------
// L1 packed weights: 32 outputs x 4 streams (WwA,WwB,WbA,WbB) x 26 f32x2 pairs
#define OFF_L1W   0                 // 3328 float2 = 26624 B
#define OFF_BW    26624             // 32 f
#define OFF_BB    26752             // 32 f
#define OFF_W0    26880             // 2048 f = 8192 B
#define OFF_B0    35072             // 32 f
#define OFF_W1    35200             // 1024 f = 4096 B
#define OFF_B1    39296             // 32 f
#define OFF_W2    39424             // 64 f = 256 B
#define OFF_UNION 39680             // max(input stage 26624 B, base 34816 B)
#define SMEM_TOTAL (39680 + 34816)  // 74496 B

__global__ void __launch_bounds__(NT, 3)
nnue_kernel(const float* __restrict__ pov, const float* __restrict__ white,
            const float* __restrict__ black,
            const float* __restrict__ Ww, const float* __restrict__ bw,
            const float* __restrict__ Wb, const float* __restrict__ bb,
            const float* __restrict__ W0, const float* __restrict__ b0,
            const float* __restrict__ W1, const float* __restrict__ b1,
            const float* __restrict__ W2, const float* __restrict__ b2,
            float* __restrict__ out, int Btot)
{
    extern __shared__ char smem[];
    const int tid = threadIdx.x;
    const long long sbase = (long long)blockIdx.x * NT;
    const long long s = sbase + tid;

    float2* l1w2 = (float2*)(smem + OFF_L1W);
    float*  bwS  = (float*)(smem + OFF_BW);
    float*  bbS  = (float*)(smem + OFF_BB);
    float*  w0S  = (float*)(smem + OFF_W0);
    float*  b0S  = (float*)(smem + OFF_B0);
    float*  w1S  = (float*)(smem + OFF_W1);
    float*  b1S  = (float*)(smem + OFF_B1);
    float*  w2S  = (float*)(smem + OFF_W2);
    float*  stW  = (float*)(smem + OFF_UNION);
    float*  stB  = stW + NT * 26;
    float*  baseS = (float*)(smem + OFF_UNION);   // reused after input packing

    // ---- stage + prepack layer-1 weights (zero-padded 49->52 per half) ----
    for (int idx = tid; idx < 3328; idx += NT) {
        int o  = idx / 104;
        int r  = idx - o * 104;
        int st = r / 26;           // 0:WwA 1:WwB 2:WbA 3:WbB
        int p  = r - st * 26;
        const float* row = ((st < 2) ? Ww : Wb) + o * 98 + ((st & 1) ? 49 : 0);
        int j0 = 2 * p;
        float lo = (j0     < 49) ? row[j0]     : 0.f;
        float hi = (j0 + 1 < 49) ? row[j0 + 1] : 0.f;
        l1w2[idx] = make_float2(lo, hi);
    }
    for (int idx = tid; idx < 2048; idx += NT) w0S[idx] = W0[idx];
    for (int idx = tid; idx < 1024; idx += NT) w1S[idx] = W1[idx];
    if (tid < 64) w2S[tid] = W2[tid];
    if (tid < 32) { bwS[tid] = bw[tid]; bbS[tid] = bb[tid];
                    b0S[tid] = b0[tid]; b1S[tid] = b1[tid]; }

    // ---- stage inputs through smem (2 chunks of 26 features), pack to regs ----
    u64 inW[26], inB[26];
    for (int c = 0; c < 2; c++) {
        __syncthreads();
        for (int idx = tid; idx < NT * 26; idx += NT) {
            int sl = idx / 26;
            int jj = idx - sl * 26;
            int j  = c * 26 + jj;
            long long g = (sbase + sl) * 49 + j;
            bool ok = (j < 49) && (sbase + sl < (long long)Btot);
            stW[idx] = ok ? white[g] : 0.f;
            stB[idx] = ok ? black[g] : 0.f;
        }
        __syncthreads();
        const u64* rw = (const u64*)(stW + tid * 26);
        const u64* rb = (const u64*)(stB + tid * 26);
        #pragma unroll
        for (int p = 0; p < 13; p++) { inW[c*13 + p] = rw[p]; inB[c*13 + p] = rb[p]; }
    }
    __syncthreads();   // all packing done before UNION region becomes baseS

    float pv = 0.f;
    if (s < (long long)Btot) pv = pov[s];
    const float pm = 1.f - pv;

    // ---- layer 1 (feature transform) + pov mix + relu ----
    const ulonglong2* l1v = (const ulonglong2*)(smem + OFF_L1W);
    #pragma unroll 1
    for (int o = 0; o < 32; o++) {
        const ulonglong2* Wv = l1v + o * 52;
        u64 aw = 0ull, ab = 0ull;
        #pragma unroll
        for (int q = 0; q < 13; q++) {
            ulonglong2 A  = Wv[q];        // WwA pairs 2q,2q+1
            ulonglong2 Bv = Wv[13 + q];   // WwB
            ulonglong2 C  = Wv[26 + q];   // WbA
            ulonglong2 D  = Wv[39 + q];   // WbB
            aw = ffma2(inW[2*q],   A.x,  aw);
            aw = ffma2(inW[2*q+1], A.y,  aw);
            aw = ffma2(inB[2*q],   Bv.x, aw);
            aw = ffma2(inB[2*q+1], Bv.y, aw);
            ab = ffma2(inB[2*q],   C.x,  ab);
            ab = ffma2(inB[2*q+1], C.y,  ab);
            ab = ffma2(inW[2*q],   D.x,  ab);
            ab = ffma2(inW[2*q+1], D.y,  ab);
        }
        float2 fw = unpk(aw), fb = unpk(ab);
        float w_ = fw.x + fw.y + bwS[o];
        float b_ = fb.x + fb.y + bbS[o];
        float vA = fmaxf(fmaf(pm, b_, pv * w_), 0.f);   // base[o]
        float vB = fmaxf(fmaf(pm, w_, pv * b_), 0.f);   // base[o+32]
        baseS[tid * 68 + o]      = vA;
        baseS[tid * 68 + 32 + o] = vB;
    }

    // ---- layer 0: x = relu(W0 @ base + b0), 8-wide output tiles ----
    float x[32];
    const ulonglong2* baseV = (const ulonglong2*)(baseS + tid * 68);
    const ulonglong2* w0v   = (const ulonglong2*)w0S;   // 16 ull2 per row
    #pragma unroll
    for (int k0 = 0; k0 < 32; k0 += 8) {
        u64 acc[8];
        #pragma unroll
        for (int kk = 0; kk < 8; kk++) acc[kk] = 0ull;
        #pragma unroll
        for (int q = 0; q < 16; q++) {
            ulonglong2 inp = baseV[q];
            #pragma unroll
            for (int kk = 0; kk < 8; kk++) {
                ulonglong2 w = w0v[(k0 + kk) * 16 + q];
                acc[kk] = ffma2(inp.x, w.x, acc[kk]);
                acc[kk] = ffma2(inp.y, w.y, acc[kk]);
            }
        }
        #pragma unroll
        for (int kk = 0; kk < 8; kk++) {
            float2 f = unpk(acc[kk]);
            x[k0 + kk] = fmaxf(f.x + f.y + b0S[k0 + kk], 0.f);
        }
    }
    u64 x2[16];
    #pragma unroll
    for (int p = 0; p < 16; p++) x2[p] = pk2(x[2*p], x[2*p+1]);

    // ---- layer 1b: y = relu(W1 @ x + b1) ----
    float y[32];
    const ulonglong2* w1v = (const ulonglong2*)w1S;   // 8 ull2 per row
    #pragma unroll
    for (int k0 = 0; k0 < 32; k0 += 8) {
        u64 acc[8];
        #pragma unroll
        for (int kk = 0; kk < 8; kk++) acc[kk] = 0ull;
        #pragma unroll
        for (int q = 0; q < 8; q++) {
            #pragma unroll
            for (int kk = 0; kk < 8; kk++) {
                ulonglong2 w = w1v[(k0 + kk) * 8 + q];
                acc[kk] = ffma2(x2[2*q],   w.x, acc[kk]);
                acc[kk] = ffma2(x2[2*q+1], w.y, acc[kk]);
            }
        }
        #pragma unroll
        for (int kk = 0; kk < 8; kk++) {
            float2 f = unpk(acc[kk]);
            y[k0 + kk] = fmaxf(f.x + f.y + b1S[k0 + kk], 0.f);
        }
    }
    u64 y2[16];
    #pragma unroll
    for (int p = 0; p < 16; p++) y2[p] = pk2(y[2*p], y[2*p+1]);

    // ---- layer 2: out = W2 @ [x; y] + b2 ----
    const ulonglong2* w2v = (const ulonglong2*)w2S;   // 16 ull2
    u64 a0 = 0ull, a1 = 0ull;
    #pragma unroll
    for (int q = 0; q < 8; q++) {
        ulonglong2 wx = w2v[q];
        ulonglong2 wy = w2v[8 + q];
        a0 = ffma2(x2[2*q],   wx.x, a0);
        a0 = ffma2(x2[2*q+1], wx.y, a0);
        a1 = ffma2(y2[2*q],   wy.x, a1);
        a1 = ffma2(y2[2*q+1], wy.y, a1);
    }
    float2 f0 = unpk(a0), f1 = unpk(a1);
    float res = f0.x + f0.y + f1.x + f1.y + b2[0];
    if (s < (long long)Btot) out[s] = res;
}

extern "C" void kernel_launch(void* const* d_in, const int* in_sizes, int n_in,
                              void* d_out, int out_size) {
    const float* pov   = (const float*)d_in[0];
    const float* white = (const float*)d_in[1];
    const float* black = (const float*)d_in[2];
    const float* Ww = (const float*)d_in[3];
    const float* bw = (const float*)d_in[4];
    const float* Wb = (const float*)d_in[5];
    const float* bb = (const float*)d_in[6];
    const float* W0 = (const float*)d_in[7];
    const float* b0 = (const float*)d_in[8];
    const float* W1 = (const float*)d_in[9];
    const float* b1 = (const float*)d_in[10];
    const float* W2 = (const float*)d_in[11];
    const float* b2 = (const float*)d_in[12];
    const int B = in_sizes[0];

    cudaFuncSetAttribute(nnue_kernel,
                         cudaFuncAttributeMaxDynamicSharedMemorySize, SMEM_TOTAL);
    int grid = (B + NT - 1) / NT;
    nnue_kernel<<<grid, NT, SMEM_TOTAL>>>(pov, white, black, Ww, bw, Wb, bb,
                                          W0, b0, W1, b1, W2, b2,
                                          (float*)d_out, B);
}

// round 3
// speedup vs baseline: 3.1326x; 3.1326x over previous
#include <cuda_runtime.h>
#include <cuda_bf16.h>
#include <stdint.h>

// ======================= fragment-packed weight image =======================
// Byte offsets inside the pack (mirrored in smem):
//  B1  frags: [8 ntile][7 ktile][32 lane] uint4 {bh0,bh1,bl0,bl1}  = 28672 B
//  B0  frags: [4][4][32] uint4                                     =  8192 B
//  B1b frags: [4][2][32] uint4                                     =  4096 B
//  bias1frag: [4 j][32] float4 {bw[c0],bw[c1],bb[c0],bb[c1]}       =  2048 B
//  b0frag:    [4 n][32] float2                                     =  1024 B
//  b1frag:    [4 n][32] float2                                     =  1024 B
//  w2frag:    [4 n][32] float4 {W2[c0],W2[c1],W2[32+c0],W2[32+c1]} =  2048 B
//  b2:        1 float (padded to 16)                               =    16 B
#define OFF_B1    0
#define OFF_B0    28672
#define OFF_B1B   36864
#define OFF_BIAS1 40960
#define OFF_B0F   43008
#define OFF_B1F   44032
#define OFF_W2F   45056
#define OFF_B2    47104
#define PACK_BYTES 47120
#define PACK_U4   (PACK_BYTES / 16)   // 2945

__device__ __align__(16) unsigned char g_pack[PACK_BYTES];

// ======================= helpers =======================
__device__ __forceinline__ uint32_t pack_bf16x2(float a, float b) {
    __nv_bfloat16 ha = __float2bfloat16(a), hb = __float2bfloat16(b);
    return (uint32_t)__bfloat16_as_ushort(ha) | ((uint32_t)__bfloat16_as_ushort(hb) << 16);
}
// split f = hi + lo (both bf16); returns via refs as floats of the bf16 values
__device__ __forceinline__ void bsplit(float f, float& h, float& l) {
    __nv_bfloat16 hb = __float2bfloat16(f);
    h = __bfloat162float(hb);
    l = f - h;   // representable accurately; second bf16 rounding happens at pack
}
// pack a pair (f0,f1) into hi-reg and lo-reg
__device__ __forceinline__ void split_pack2(float f0, float f1, uint32_t& hr, uint32_t& lr) {
    float h0, l0, h1, l1;
    bsplit(f0, h0, l0);
    bsplit(f1, h1, l1);
    hr = pack_bf16x2(h0, h1);
    lr = pack_bf16x2(l0, l1);
}

__device__ __forceinline__ void mma16816(float* c, const uint32_t* a, uint32_t b0, uint32_t b1) {
    asm volatile(
        "mma.sync.aligned.m16n8k16.row.col.f32.bf16.bf16.f32 "
        "{%0,%1,%2,%3}, {%4,%5,%6,%7}, {%8,%9}, {%0,%1,%2,%3};"
        : "+f"(c[0]), "+f"(c[1]), "+f"(c[2]), "+f"(c[3])
        : "r"(a[0]), "r"(a[1]), "r"(a[2]), "r"(a[3]), "r"(b0), "r"(b1));
}

// ======================= prep kernel (weight fragment packing) =======================
__device__ __forceinline__ float getW1c(const float* Ww, const float* Wb, int n, int k) {
    if (k >= 98) return 0.f;
    if (n < 32) return Ww[n * 98 + k];
    int kk = k + 49; if (kk >= 98) kk -= 98;
    return Wb[(n - 32) * 98 + kk];
}

__global__ void prep_kernel(const float* __restrict__ Ww, const float* __restrict__ Wb,
                            const float* __restrict__ W0, const float* __restrict__ W1,
                            const float* __restrict__ bw, const float* __restrict__ bb,
                            const float* __restrict__ b0, const float* __restrict__ b1,
                            const float* __restrict__ W2, const float* __restrict__ b2)
{
    const int tid = threadIdx.x;  // 256 threads, 1 block
    char* gp = (char*)g_pack;

    // B1 frags
    for (int idx = tid; idx < 8 * 7 * 32; idx += 256) {
        int lane = idx & 31, t = idx >> 5;
        int kt = t % 7, nt = t / 7;
        int n = nt * 8 + (lane >> 2);
        int k0 = kt * 16 + (lane & 3) * 2;
        float w[4] = { getW1c(Ww, Wb, n, k0),     getW1c(Ww, Wb, n, k0 + 1),
                       getW1c(Ww, Wb, n, k0 + 8), getW1c(Ww, Wb, n, k0 + 9) };
        float h[4], l[4];
        for (int i = 0; i < 4; i++) bsplit(w[i], h[i], l[i]);
        uint4 v;
        v.x = pack_bf16x2(h[0], h[1]); v.y = pack_bf16x2(h[2], h[3]);
        v.z = pack_bf16x2(l[0], l[1]); v.w = pack_bf16x2(l[2], l[3]);
        ((uint4*)(gp + OFF_B1))[idx] = v;
    }
    // B0 frags (N=32,K=64)
    for (int idx = tid; idx < 4 * 4 * 32; idx += 256) {
        int lane = idx & 31, t = idx >> 5;
        int kt = t & 3, nt = t >> 2;
        int n = nt * 8 + (lane >> 2);
        int k0 = kt * 16 + (lane & 3) * 2;
        float w[4] = { W0[n * 64 + k0],     W0[n * 64 + k0 + 1],
                       W0[n * 64 + k0 + 8], W0[n * 64 + k0 + 9] };
        float h[4], l[4];
        for (int i = 0; i < 4; i++) bsplit(w[i], h[i], l[i]);
        uint4 v;
        v.x = pack_bf16x2(h[0], h[1]); v.y = pack_bf16x2(h[2], h[3]);
        v.z = pack_bf16x2(l[0], l[1]); v.w = pack_bf16x2(l[2], l[3]);
        ((uint4*)(gp + OFF_B0))[idx] = v;
    }
    // B1b frags (N=32,K=32)
    for (int idx = tid; idx < 4 * 2 * 32; idx += 256) {
        int lane = idx & 31, t = idx >> 5;
        int kt = t & 1, nt = t >> 1;
        int n = nt * 8 + (lane >> 2);
        int k0 = kt * 16 + (lane & 3) * 2;
        float w[4] = { W1[n * 32 + k0],     W1[n * 32 + k0 + 1],
                       W1[n * 32 + k0 + 8], W1[n * 32 + k0 + 9] };
        float h[4], l[4];
        for (int i = 0; i < 4; i++) bsplit(w[i], h[i], l[i]);
        uint4 v;
        v.x = pack_bf16x2(h[0], h[1]); v.y = pack_bf16x2(h[2], h[3]);
        v.z = pack_bf16x2(l[0], l[1]); v.w = pack_bf16x2(l[2], l[3]);
        ((uint4*)(gp + OFF_B1B))[idx] = v;
    }
    // bias / W2 frags
    for (int idx = tid; idx < 4 * 32; idx += 256) {
        int lane = idx & 31, j = idx >> 5;
        int c = j * 8 + (lane & 3) * 2;
        float4 bf; bf.x = bw[c]; bf.y = bw[c + 1]; bf.z = bb[c]; bf.w = bb[c + 1];
        ((float4*)(gp + OFF_BIAS1))[idx] = bf;
        float2 f0; f0.x = b0[c]; f0.y = b0[c + 1];
        ((float2*)(gp + OFF_B0F))[idx] = f0;
        float2 f1; f1.x = b1[c]; f1.y = b1[c + 1];
        ((float2*)(gp + OFF_B1F))[idx] = f1;
        float4 w2; w2.x = W2[c]; w2.y = W2[c + 1]; w2.z = W2[32 + c]; w2.w = W2[32 + c + 1];
        ((float4*)(gp + OFF_W2F))[idx] = w2;
    }
    if (tid == 0) *((float*)(gp + OFF_B2)) = b2[0];
}

// ======================= main fused kernel =======================
__device__ __forceinline__ float getA(const float* __restrict__ wht,
                                      const float* __restrict__ blk,
                                      long long row, int c) {
    if (c < 49) return wht[row * 49 + c];
    if (c < 98) return blk[row * 49 + (c - 49)];
    return 0.f;
}

__global__ void __launch_bounds__(128, 3)
nnue_main(const float* __restrict__ pov, const float* __restrict__ white,
          const float* __restrict__ black, float* __restrict__ out, int Btot)
{
    __shared__ __align__(16) unsigned char spack[PACK_BYTES];

    const int tid  = threadIdx.x;
    const int warp = tid >> 5;
    const int lane = tid & 31;
    const long long cbase = (long long)blockIdx.x * 128;

    // copy fragment pack into smem (L2-hot broadcast)
    {
        const uint4* src = (const uint4*)g_pack;
        uint4* dst = (uint4*)spack;
        for (int i = tid; i < PACK_U4; i += 128) dst[i] = src[i];
    }
    __syncthreads();

    const char* sp = (const char*)spack;
    const uint4*  B1u  = (const uint4*)(sp + OFF_B1);
    const uint4*  B0u  = (const uint4*)(sp + OFF_B0);
    const uint4*  B1bu = (const uint4*)(sp + OFF_B1B);
    const float4* bia1 = (const float4*)(sp + OFF_BIAS1);
    const float2* b0f  = (const float2*)(sp + OFF_B0F);
    const float2* b1f  = (const float2*)(sp + OFF_B1F);
    const float4* w2f  = (const float4*)(sp + OFF_W2F);
    const float   b2v  = *((const float*)(sp + OFF_B2));

    const int q = lane >> 2;          // quad row index 0..7
    const int qp = lane & 3;          // position in quad

    #pragma unroll 1
    for (int mi = 0; mi < 2; mi++) {
        const int mt = warp * 2 + mi;
        long long row0 = cbase + mt * 16 + q;      // rows q and q+8 of the m-tile
        long long row1 = row0 + 8;
        long long r0c = row0 < (long long)Btot ? row0 : (long long)Btot - 1;
        long long r1c = row1 < (long long)Btot ? row1 : (long long)Btot - 1;

        float pv0 = pov[r0c], pv1 = pov[r1c];
        float pm0 = 1.f - pv0, pm1 = 1.f - pv1;

        // ---- build layer-1 A fragments (hi/lo) ----
        uint32_t ah[7][4], al[7][4];
        #pragma unroll
        for (int kt = 0; kt < 7; kt++) {
            int c = kt * 16 + qp * 2;
            float f00 = getA(white, black, r0c, c);
            float f01 = getA(white, black, r0c, c + 1);
            float f08 = getA(white, black, r0c, c + 8);
            float f09 = getA(white, black, r0c, c + 9);
            float f10 = getA(white, black, r1c, c);
            float f11 = getA(white, black, r1c, c + 1);
            float f18 = getA(white, black, r1c, c + 8);
            float f19 = getA(white, black, r1c, c + 9);
            split_pack2(f00, f01, ah[kt][0], al[kt][0]);
            split_pack2(f10, f11, ah[kt][1], al[kt][1]);
            split_pack2(f08, f09, ah[kt][2], al[kt][2]);
            split_pack2(f18, f19, ah[kt][3], al[kt][3]);
        }

        // ---- layer 1 + epilogue1 -> layer-0 A fragments ----
        uint32_t a0h[4][4], a0l[4][4];
        #pragma unroll
        for (int j = 0; j < 4; j++) {
            float cw[4] = {0.f, 0.f, 0.f, 0.f};
            float cb[4] = {0.f, 0.f, 0.f, 0.f};
            #pragma unroll
            for (int kt = 0; kt < 7; kt++) {
                uint4 Bw = B1u[(j * 7 + kt) * 32 + lane];
                uint4 Bb = B1u[((j + 4) * 7 + kt) * 32 + lane];
                mma16816(cw, ah[kt], Bw.x, Bw.y);
                mma16816(cw, al[kt], Bw.x, Bw.y);
                mma16816(cw, ah[kt], Bw.z, Bw.w);
                mma16816(cb, ah[kt], Bb.x, Bb.y);
                mma16816(cb, al[kt], Bb.x, Bb.y);
                mma16816(cb, ah[kt], Bb.z, Bb.w);
            }
            float4 bi = bia1[j * 32 + lane];
            float w0 = cw[0] + bi.x, w1 = cw[1] + bi.y;
            float w2_ = cw[2] + bi.x, w3 = cw[3] + bi.y;
            float bb0 = cb[0] + bi.z, bb1 = cb[1] + bi.w;
            float bb2 = cb[2] + bi.z, bb3 = cb[3] + bi.w;
            // base col j*8.. (w-side): pv*w + (1-pv)*b ; col+32 (b-side): swapped
            float vA0 = fmaxf(fmaf(pv0, w0, pm0 * bb0), 0.f);
            float vA1 = fmaxf(fmaf(pv0, w1, pm0 * bb1), 0.f);
            float vA2 = fmaxf(fmaf(pv1, w2_, pm1 * bb2), 0.f);
            float vA3 = fmaxf(fmaf(pv1, w3, pm1 * bb3), 0.f);
            float vB0 = fmaxf(fmaf(pv0, bb0, pm0 * w0), 0.f);
            float vB1 = fmaxf(fmaf(pv0, bb1, pm0 * w1), 0.f);
            float vB2 = fmaxf(fmaf(pv1, bb2, pm1 * w2_), 0.f);
            float vB3 = fmaxf(fmaf(pv1, bb3, pm1 * w3), 0.f);
            int ktw = j >> 1;
            int pos = (j & 1) ? 2 : 0;  // a0/a1 vs a2/a3
            split_pack2(vA0, vA1, a0h[ktw][pos],     a0l[ktw][pos]);
            split_pack2(vA2, vA3, a0h[ktw][pos + 1], a0l[ktw][pos + 1]);
            split_pack2(vB0, vB1, a0h[ktw + 2][pos],     a0l[ktw + 2][pos]);
            split_pack2(vB2, vB3, a0h[ktw + 2][pos + 1], a0l[ktw + 2][pos + 1]);
        }

        // ---- layer 0 + epilogue -> x (fp32) and layer-1b A frags ----
        float xv[4][4];
        uint32_t a1h[2][4], a1l[2][4];
        #pragma unroll
        for (int n = 0; n < 4; n++) {
            float c0[4] = {0.f, 0.f, 0.f, 0.f};
            #pragma unroll
            for (int kt = 0; kt < 4; kt++) {
                uint4 Bq = B0u[(n * 4 + kt) * 32 + lane];
                mma16816(c0, a0h[kt], Bq.x, Bq.y);
                mma16816(c0, a0l[kt], Bq.x, Bq.y);
                mma16816(c0, a0h[kt], Bq.z, Bq.w);
            }
            float2 bz = b0f[n * 32 + lane];
            float x0 = fmaxf(c0[0] + bz.x, 0.f);
            float x1 = fmaxf(c0[1] + bz.y, 0.f);
            float x2 = fmaxf(c0[2] + bz.x, 0.f);
            float x3 = fmaxf(c0[3] + bz.y, 0.f);
            xv[n][0] = x0; xv[n][1] = x1; xv[n][2] = x2; xv[n][3] = x3;
            int ktw = n >> 1;
            int pos = (n & 1) ? 2 : 0;
            split_pack2(x0, x1, a1h[ktw][pos],     a1l[ktw][pos]);
            split_pack2(x2, x3, a1h[ktw][pos + 1], a1l[ktw][pos + 1]);
        }

        // ---- layer 1b + final dot (fused) ----
        float rA = 0.f, rB = 0.f;
        #pragma unroll
        for (int n = 0; n < 4; n++) {
            float c1[4] = {0.f, 0.f, 0.f, 0.f};
            #pragma unroll
            for (int kt = 0; kt < 2; kt++) {
                uint4 Bq = B1bu[(n * 2 + kt) * 32 + lane];
                mma16816(c1, a1h[kt], Bq.x, Bq.y);
                mma16816(c1, a1l[kt], Bq.x, Bq.y);
                mma16816(c1, a1h[kt], Bq.z, Bq.w);
            }
            float2 bz = b1f[n * 32 + lane];
            float y0 = fmaxf(c1[0] + bz.x, 0.f);
            float y1 = fmaxf(c1[1] + bz.y, 0.f);
            float y2 = fmaxf(c1[2] + bz.x, 0.f);
            float y3 = fmaxf(c1[3] + bz.y, 0.f);
            float4 w2 = w2f[n * 32 + lane];
            rA = fmaf(w2.x, xv[n][0], rA); rA = fmaf(w2.y, xv[n][1], rA);
            rA = fmaf(w2.z, y0, rA);       rA = fmaf(w2.w, y1, rA);
            rB = fmaf(w2.x, xv[n][2], rB); rB = fmaf(w2.y, xv[n][3], rB);
            rB = fmaf(w2.z, y2, rB);       rB = fmaf(w2.w, y3, rB);
        }
        // quad reduction (lanes sharing the same rows)
        rA += __shfl_xor_sync(0xFFFFFFFFu, rA, 1);
        rA += __shfl_xor_sync(0xFFFFFFFFu, rA, 2);
        rB += __shfl_xor_sync(0xFFFFFFFFu, rB, 1);
        rB += __shfl_xor_sync(0xFFFFFFFFu, rB, 2);
        if (qp == 0) {
            if (row0 < (long long)Btot) out[row0] = rA + b2v;
            if (row1 < (long long)Btot) out[row1] = rB + b2v;
        }
    }
}

// ======================= launch =======================
extern "C" void kernel_launch(void* const* d_in, const int* in_sizes, int n_in,
                              void* d_out, int out_size) {
    const float* pov   = (const float*)d_in[0];
    const float* white = (const float*)d_in[1];
    const float* black = (const float*)d_in[2];
    const float* Ww = (const float*)d_in[3];
    const float* bw = (const float*)d_in[4];
    const float* Wb = (const float*)d_in[5];
    const float* bb = (const float*)d_in[6];
    const float* W0 = (const float*)d_in[7];
    const float* b0 = (const float*)d_in[8];
    const float* W1 = (const float*)d_in[9];
    const float* b1 = (const float*)d_in[10];
    const float* W2 = (const float*)d_in[11];
    const float* b2 = (const float*)d_in[12];
    const int B = in_sizes[0];

    prep_kernel<<<1, 256>>>(Ww, Wb, W0, W1, bw, bb, b0, b1, W2, b2);
    int grid = (B + 127) >> 7;
    nnue_main<<<grid, 128>>>(pov, white, black, (float*)d_out, B);
}